// round 3
// baseline (speedup 1.0000x reference)
#include <cuda_runtime.h>
#include <math.h>

#define NN   50000
#define EE   800000
#define FIN  128
#define HDIM 256
#define NHD  4
#define NCLS 40
#define ETOT (EE + NN)
#define FULL 0xffffffffu

// ---------------- scratch (no allocations allowed) ----------------
__device__ __align__(16) float g_h[(size_t)NN * HDIM];   // GEMM output / agg input
__device__ __align__(16) float g_t[(size_t)NN * HDIM];   // agg output / next GEMM input
__device__ float g_as[NN * NHD];
__device__ float g_ad[NN * NHD];
__device__ int   g_deg[NN];
__device__ int   g_rowptr[NN + 1];
__device__ int   g_cursor[NN];
__device__ int   g_col[ETOT];
__device__ int   g_is64;

// ---------------- edge dtype detector ----------------
// If the buffer is int64 (values in [0,NN)), every int64 read is in range.
// If it is int32, int64 reads combine pairs (a + b*2^32) with b a random node
// id (nonzero w.h.p. within 128 samples) -> out of range -> flag int32.
__global__ void k_detect(const void* eiv) {
    if (threadIdx.x == 0 && blockIdx.x == 0) {
        const long long* p = (const long long*)eiv;
        int ok64 = 1;
        for (int i = 0; i < 128; i++) {
            long long v = p[i];
            if (v < 0 || v >= NN) { ok64 = 0; break; }
        }
        g_is64 = ok64;
    }
}

__device__ __forceinline__ int edge_at(const void* eiv, int idx) {
    if (g_is64) return (int)((const long long*)eiv)[idx];
    return ((const int*)eiv)[idx];
}

// ---------------- CSR build ----------------
__global__ void k_deg_init() {
    int i = blockIdx.x * blockDim.x + threadIdx.x;
    if (i < NN) g_deg[i] = 1;  // self-loop
}

__global__ void k_deg_count(const void* __restrict__ eiv) {
    int e = blockIdx.x * blockDim.x + threadIdx.x;
    if (e < EE) {
        int d = edge_at(eiv, EE + e);
        atomicAdd(&g_deg[d], 1);
    }
}

__global__ void k_scan() {
    __shared__ int sh[1024];
    __shared__ int carry_s;
    int tid = threadIdx.x;
    if (tid == 0) carry_s = 0;
    __syncthreads();
    const int nch = (NN + 1023) / 1024;
    for (int c = 0; c < nch; c++) {
        int i = c * 1024 + tid;
        int v = (i < NN) ? g_deg[i] : 0;
        sh[tid] = v;
        __syncthreads();
        for (int off = 1; off < 1024; off <<= 1) {
            int t = (tid >= off) ? sh[tid - off] : 0;
            __syncthreads();
            sh[tid] += t;
            __syncthreads();
        }
        int carry = carry_s;
        int excl = sh[tid] - v;
        if (i < NN) {
            g_rowptr[i] = carry + excl;
            g_cursor[i] = carry + excl;
        }
        __syncthreads();
        if (tid == 1023) carry_s = carry + sh[1023];
        __syncthreads();
    }
    if (tid == 0) g_rowptr[NN] = carry_s;
}

__global__ void k_fill(const void* __restrict__ eiv) {
    int t = blockIdx.x * blockDim.x + threadIdx.x;
    if (t < EE) {
        int s = edge_at(eiv, t);
        int d = edge_at(eiv, EE + t);
        int p = atomicAdd(&g_cursor[d], 1);
        g_col[p] = s;
    } else if (t < ETOT) {
        int n = t - EE;
        int p = atomicAdd(&g_cursor[n], 1);
        g_col[p] = n;
    }
}

// ---------------- SGEMM: C[M,Nc] = A[M,K] @ B[K,Nc] ----------------
#define BM 128
#define BN 128
#define BKK 16
#define TM 8
#define TN 8

__global__ __launch_bounds__(256) void k_sgemm(const float* __restrict__ A,
                                               const float* __restrict__ B,
                                               float* __restrict__ C,
                                               int M, int K, int Nc) {
    __shared__ float As[BKK][BM];
    __shared__ float Bs[BKK][BN];
    int tid = threadIdx.x;
    int bx = blockIdx.x, by = blockIdx.y;
    int tx = tid % 16, ty = tid / 16;

    int aRow  = tid / 4;          // 0..63
    int aCol4 = (tid % 4) * 4;    // 0,4,8,12
    int bRow  = tid / 32;         // 0..7
    int bCol4 = (tid % 32) * 4;

    float acc[TM][TN];
#pragma unroll
    for (int i = 0; i < TM; i++)
#pragma unroll
        for (int j = 0; j < TN; j++) acc[i][j] = 0.f;

    const float* Ablk = A + (size_t)(by * BM) * K;
    const float* Bblk = B + bx * BN;

    for (int k0 = 0; k0 < K; k0 += BKK) {
#pragma unroll
        for (int r = 0; r < BM; r += 64) {
            int row = aRow + r;
            int grow = by * BM + row;
            float4 v = make_float4(0.f, 0.f, 0.f, 0.f);
            if (grow < M)
                v = *reinterpret_cast<const float4*>(Ablk + (size_t)row * K + k0 + aCol4);
            As[aCol4 + 0][row] = v.x;
            As[aCol4 + 1][row] = v.y;
            As[aCol4 + 2][row] = v.z;
            As[aCol4 + 3][row] = v.w;
        }
#pragma unroll
        for (int r = 0; r < BKK; r += 8) {
            int row = bRow + r;
            float4 v = *reinterpret_cast<const float4*>(Bblk + (size_t)(k0 + row) * Nc + bCol4);
            *reinterpret_cast<float4*>(&Bs[row][bCol4]) = v;
        }
        __syncthreads();
#pragma unroll
        for (int kk = 0; kk < BKK; kk++) {
            float ra[TM], rb[TN];
#pragma unroll
            for (int i = 0; i < TM; i++) ra[i] = As[kk][ty * TM + i];
#pragma unroll
            for (int j = 0; j < TN; j++) rb[j] = Bs[kk][tx * TN + j];
#pragma unroll
            for (int i = 0; i < TM; i++)
#pragma unroll
                for (int j = 0; j < TN; j++) acc[i][j] += ra[i] * rb[j];
        }
        __syncthreads();
    }

#pragma unroll
    for (int i = 0; i < TM; i++) {
        int grow = by * BM + ty * TM + i;
        if (grow < M) {
            float4 v0 = make_float4(acc[i][0], acc[i][1], acc[i][2], acc[i][3]);
            float4 v1 = make_float4(acc[i][4], acc[i][5], acc[i][6], acc[i][7]);
            float* cp = C + (size_t)grow * Nc + bx * BN + tx * TN;
            *reinterpret_cast<float4*>(cp)     = v0;
            *reinterpret_cast<float4*>(cp + 4) = v1;
        }
    }
}

// ---------------- per-node attention logits: alpha_s, alpha_d ----------------
__global__ void k_alpha(const float* __restrict__ h,
                        const float* __restrict__ avs,
                        const float* __restrict__ avd) {
    int gw = (blockIdx.x * blockDim.x + threadIdx.x) >> 5;
    int lane = threadIdx.x & 31;
    if (gw >= NN) return;
    const float* hr = h + (size_t)gw * HDIM;
    float accS[4] = {0.f, 0.f, 0.f, 0.f};
    float accD[4] = {0.f, 0.f, 0.f, 0.f};
#pragma unroll
    for (int k = 0; k < 8; k++) {
        int f = lane + 32 * k;
        float hv = hr[f];
        accS[k >> 1] += hv * __ldg(&avs[f]);
        accD[k >> 1] += hv * __ldg(&avd[f]);
    }
#pragma unroll
    for (int off = 16; off >= 1; off >>= 1) {
#pragma unroll
        for (int hh = 0; hh < 4; hh++) {
            accS[hh] += __shfl_xor_sync(FULL, accS[hh], off);
            accD[hh] += __shfl_xor_sync(FULL, accD[hh], off);
        }
    }
    if (lane == 0) {
#pragma unroll
        for (int hh = 0; hh < 4; hh++) {
            g_as[gw * 4 + hh] = accS[hh];
            g_ad[gw * 4 + hh] = accD[hh];
        }
    }
}

// ---------------- one-pass online-softmax aggregation (warp per dst node) ----
__global__ void k_agg(const float* __restrict__ h,
                      const float* __restrict__ bias,
                      float* __restrict__ out, int elu) {
    int gw = (blockIdx.x * blockDim.x + threadIdx.x) >> 5;
    int lane = threadIdx.x & 31;
    if (gw >= NN) return;

    float adl = (lane < 4) ? g_ad[gw * 4 + lane] : 0.f;
    int jb = __ldg(&g_rowptr[gw]), je = __ldg(&g_rowptr[gw + 1]);

    float acc[8] = {0.f, 0.f, 0.f, 0.f, 0.f, 0.f, 0.f, 0.f};
    float m[4] = {-INFINITY, -INFINITY, -INFINITY, -INFINITY};
    float ssum[4] = {0.f, 0.f, 0.f, 0.f};

    int src_next = (jb < je) ? __ldg(&g_col[jb]) : 0;
    for (int j = jb; j < je; j++) {
        int src = src_next;
        if (j + 1 < je) src_next = __ldg(&g_col[j + 1]);  // prefetch next index

        float ev = 0.f;
        if (lane < 4) {
            float e = __ldg(&g_as[src * 4 + lane]) + adl;
            ev = e > 0.f ? e : 0.2f * e;  // leaky relu
        }
        float e4[4];
        e4[0] = __shfl_sync(FULL, ev, 0);
        e4[1] = __shfl_sync(FULL, ev, 1);
        e4[2] = __shfl_sync(FULL, ev, 2);
        e4[3] = __shfl_sync(FULL, ev, 3);

        float sc[4], w[4];
#pragma unroll
        for (int hh = 0; hh < 4; hh++) {
            if (e4[hh] <= m[hh]) {
                sc[hh] = 1.f;
                w[hh] = __expf(e4[hh] - m[hh]);
            } else {
                sc[hh] = __expf(m[hh] - e4[hh]);  // exp(-inf)=0 on first edge
                w[hh] = 1.f;
                m[hh] = e4[hh];
            }
            ssum[hh] = ssum[hh] * sc[hh] + w[hh];
        }
        const float* hr = h + (size_t)src * HDIM + lane;
#pragma unroll
        for (int k = 0; k < 8; k++) {
            float xv = __ldg(hr + 32 * k);
            int hh = k >> 1;
            acc[k] = acc[k] * sc[hh] + w[hh] * xv;
        }
    }
#pragma unroll
    for (int k = 0; k < 8; k++) {
        int f = lane + 32 * k;
        int hh = k >> 1;
        float v = acc[k] / (ssum[hh] + 1e-16f) + __ldg(&bias[f]);
        if (elu) v = v > 0.f ? v : expm1f(v);
        out[(size_t)gw * HDIM + f] = v;
    }
}

// ---------------- final linear + log_softmax (warp per node) ----------------
__global__ void k_final(const float* __restrict__ h,
                        const float* __restrict__ Wl,
                        const float* __restrict__ bl,
                        float* __restrict__ out) {
    int gw = (blockIdx.x * blockDim.x + threadIdx.x) >> 5;
    int lane = threadIdx.x & 31;
    if (gw >= NN) return;

    int c0 = lane;
    int c1 = lane + 32;
    bool v1 = (c1 < NCLS);
    float a0 = __ldg(&bl[c0]);
    float a1 = v1 ? __ldg(&bl[c1]) : 0.f;
    const float* hr = h + (size_t)gw * HDIM;

    for (int kb = 0; kb < 8; kb++) {
        float xv = hr[kb * 32 + lane];
#pragma unroll
        for (int t = 0; t < 32; t++) {
            float xk = __shfl_sync(FULL, xv, t);
            int k = kb * 32 + t;
            a0 += xk * __ldg(&Wl[k * NCLS + c0]);
            if (v1) a1 += xk * __ldg(&Wl[k * NCLS + c1]);
        }
    }
    float mx = v1 ? fmaxf(a0, a1) : a0;
#pragma unroll
    for (int off = 16; off >= 1; off >>= 1) mx = fmaxf(mx, __shfl_xor_sync(FULL, mx, off));
    float se = __expf(a0 - mx) + (v1 ? __expf(a1 - mx) : 0.f);
#pragma unroll
    for (int off = 16; off >= 1; off >>= 1) se += __shfl_xor_sync(FULL, se, off);
    float lse = mx + __logf(se);
    out[(size_t)gw * NCLS + c0] = a0 - lse;
    if (v1) out[(size_t)gw * NCLS + c1] = a1 - lse;
}

// ---------------- launcher ----------------
extern "C" void kernel_launch(void* const* d_in, const int* in_sizes, int n_in,
                              void* d_out, int out_size) {
    const float* x   = (const float*)d_in[0];
    const void*  ei  = d_in[1];   // int32 or int64, detected on device
    const float* W1  = (const float*)d_in[2];
    const float* as1 = (const float*)d_in[3];
    const float* ad1 = (const float*)d_in[4];
    const float* b1  = (const float*)d_in[5];
    const float* W2  = (const float*)d_in[6];
    const float* as2 = (const float*)d_in[7];
    const float* ad2 = (const float*)d_in[8];
    const float* b2  = (const float*)d_in[9];
    const float* W3  = (const float*)d_in[10];
    const float* as3 = (const float*)d_in[11];
    const float* ad3 = (const float*)d_in[12];
    const float* b3  = (const float*)d_in[13];
    const float* Wl  = (const float*)d_in[14];
    const float* bl  = (const float*)d_in[15];
    float* out = (float*)d_out;

    float *ph, *pt;
    cudaGetSymbolAddress((void**)&ph, g_h);
    cudaGetSymbolAddress((void**)&pt, g_t);

    // CSR build
    k_detect<<<1, 32>>>(ei);
    k_deg_init<<<(NN + 255) / 256, 256>>>();
    k_deg_count<<<(EE + 255) / 256, 256>>>(ei);
    k_scan<<<1, 1024>>>();
    k_fill<<<(ETOT + 255) / 256, 256>>>(ei);

    dim3 gemmGrid(HDIM / BN, (NN + BM - 1) / BM);
    const int wgrid = (NN * 32 + 255) / 256;  // 6250 blocks, warp per node

    // layer 1
    k_sgemm<<<gemmGrid, 256>>>(x, W1, ph, NN, FIN, HDIM);
    k_alpha<<<wgrid, 256>>>(ph, as1, ad1);
    k_agg<<<wgrid, 256>>>(ph, b1, pt, 1);
    // layer 2
    k_sgemm<<<gemmGrid, 256>>>(pt, W2, ph, NN, HDIM, HDIM);
    k_alpha<<<wgrid, 256>>>(ph, as2, ad2);
    k_agg<<<wgrid, 256>>>(ph, b2, pt, 1);
    // layer 3
    k_sgemm<<<gemmGrid, 256>>>(pt, W3, ph, NN, HDIM, HDIM);
    k_alpha<<<wgrid, 256>>>(ph, as3, ad3);
    k_agg<<<wgrid, 256>>>(ph, b3, pt, 1);
    // classifier + log_softmax
    k_final<<<wgrid, 256>>>(pt, Wl, bl, out);
}

// round 4
// speedup vs baseline: 1.1070x; 1.1070x over previous
#include <cuda_runtime.h>
#include <math.h>
#include <stdint.h>

#define NN   50000
#define EE   800000
#define FIN  128
#define HDIM 256
#define NHD  4
#define NCLS 40
#define ETOT (EE + NN)
#define FULL 0xffffffffu

#define SCB   1024
#define NBLK  ((NN + SCB - 1) / SCB)

// ---------------- scratch (no allocations allowed) ----------------
__device__ __align__(16) float g_h[(size_t)NN * HDIM];
__device__ __align__(16) float g_t[(size_t)NN * HDIM];
__device__ float g_as[NN * NHD];
__device__ float g_ad[NN * NHD];
__device__ int   g_deg[NN];
__device__ int   g_rowptr[NN + 1];
__device__ int   g_cursor[NN];
__device__ int   g_col[ETOT];
__device__ int   g_part[NBLK];
__device__ int   g_is64;

// ---------------- edge dtype detector ----------------
__global__ void k_detect(const void* eiv) {
    if (threadIdx.x == 0 && blockIdx.x == 0) {
        const long long* p = (const long long*)eiv;
        int ok64 = 1;
        for (int i = 0; i < 128; i++) {
            long long v = p[i];
            if (v < 0 || v >= NN) { ok64 = 0; break; }
        }
        g_is64 = ok64;
    }
}

__device__ __forceinline__ int edge_at(const void* eiv, int idx) {
    if (g_is64) return (int)((const long long*)eiv)[idx];
    return ((const int*)eiv)[idx];
}

// ---------------- CSR build ----------------
__global__ void k_deg_init() {
    int i = blockIdx.x * blockDim.x + threadIdx.x;
    if (i < NN) g_deg[i] = 1;  // self-loop
}

__global__ void k_deg_count(const void* __restrict__ eiv) {
    int e = blockIdx.x * blockDim.x + threadIdx.x;
    if (e < EE) {
        int d = edge_at(eiv, EE + e);
        atomicAdd(&g_deg[d], 1);
    }
}

// phase 1: per-block exclusive scan, block totals to g_part
__global__ void k_scan1() {
    __shared__ int sh[SCB];
    int b = blockIdx.x, tid = threadIdx.x;
    int i = b * SCB + tid;
    int v = (i < NN) ? g_deg[i] : 0;
    sh[tid] = v;
    __syncthreads();
    for (int off = 1; off < SCB; off <<= 1) {
        int t = (tid >= off) ? sh[tid - off] : 0;
        __syncthreads();
        sh[tid] += t;
        __syncthreads();
    }
    if (i < NN) g_rowptr[i] = sh[tid] - v;
    if (tid == SCB - 1) g_part[b] = sh[tid];
}

// phase 2: scan the 49 block partials (tiny, serial)
__global__ void k_scan2() {
    if (threadIdx.x == 0) {
        int s = 0;
        for (int b = 0; b < NBLK; b++) { int t = g_part[b]; g_part[b] = s; s += t; }
        g_rowptr[NN] = s;
    }
}

// phase 3: add block offsets, init cursors
__global__ void k_scan3() {
    int i = blockIdx.x * blockDim.x + threadIdx.x;
    if (i < NN) {
        int r = g_rowptr[i] + g_part[i >> 10];
        g_rowptr[i] = r;
        g_cursor[i] = r;
    }
}

__global__ void k_fill(const void* __restrict__ eiv) {
    int t = blockIdx.x * blockDim.x + threadIdx.x;
    if (t < EE) {
        int s = edge_at(eiv, t);
        int d = edge_at(eiv, EE + t);
        int p = atomicAdd(&g_cursor[d], 1);
        g_col[p] = s;
    } else if (t < ETOT) {
        int n = t - EE;
        int p = atomicAdd(&g_cursor[n], 1);
        g_col[p] = n;
    }
}

// ---------------- TF32x3 tensor-core GEMM: C[M,256] = A[M,K] @ B[K,256] -----
// block tile 128x128, BK=8, double buffered; 8 warps, warp tile 32(M)x64(N)
#define GBM 128
#define GBN 128
#define GBK 8
#define APAD 12
#define BPAD 136

__device__ __forceinline__ uint32_t f2tf(float x) {
    uint32_t u;
    asm("cvt.rna.tf32.f32 %0, %1;" : "=r"(u) : "f"(x));
    return u;
}

__device__ __forceinline__ void mma8(float* c, const uint32_t* a, const uint32_t* b) {
    asm volatile(
        "mma.sync.aligned.m16n8k8.row.col.f32.tf32.tf32.f32 "
        "{%0,%1,%2,%3}, {%4,%5,%6,%7}, {%8,%9}, {%0,%1,%2,%3};"
        : "+f"(c[0]), "+f"(c[1]), "+f"(c[2]), "+f"(c[3])
        : "r"(a[0]), "r"(a[1]), "r"(a[2]), "r"(a[3]), "r"(b[0]), "r"(b[1]));
}

__global__ __launch_bounds__(256) void k_mma(const float* __restrict__ A,
                                             const float* __restrict__ B,
                                             float* __restrict__ C,
                                             int M, int K) {
    __shared__ uint32_t Ah[2][GBM][APAD];
    __shared__ uint32_t Al[2][GBM][APAD];
    __shared__ uint32_t Bh[2][GBK][BPAD];
    __shared__ uint32_t Bl[2][GBK][BPAD];

    int tid = threadIdx.x;
    int lane = tid & 31;
    int warp = tid >> 5;
    int wm = warp & 3;           // 0..3 -> 32-row slice
    int wn = warp >> 2;          // 0..1 -> 64-col slice
    int bx = blockIdx.x, by = blockIdx.y;

    int g = lane >> 2;           // groupID
    int tg = lane & 3;           // thread-in-group

    // global load indices
    int aRow = tid >> 1;                 // 0..127
    int aCol = (tid & 1) * 4;            // 0 or 4
    int bK   = tid >> 5;                 // 0..7
    int bCol = (tid & 31) * 4;           // 0..124

    float acc[2][8][4];
#pragma unroll
    for (int mt = 0; mt < 2; mt++)
#pragma unroll
        for (int nt = 0; nt < 8; nt++)
#pragma unroll
            for (int q = 0; q < 4; q++) acc[mt][nt][q] = 0.f;

    const float* Ablk = A + (size_t)(by * GBM) * K;
    const float* Bblk = B + bx * GBN;
    int nch = K / GBK;

    int grow0 = by * GBM + aRow;
    float4 ra, rb;
    // prefetch chunk 0
    ra = make_float4(0.f, 0.f, 0.f, 0.f);
    if (grow0 < M) ra = *reinterpret_cast<const float4*>(Ablk + (size_t)aRow * K + aCol);
    rb = *reinterpret_cast<const float4*>(Bblk + (size_t)bK * HDIM + bCol);

    // convert + store chunk 0
    {
        float av[4] = {ra.x, ra.y, ra.z, ra.w};
        float bv[4] = {rb.x, rb.y, rb.z, rb.w};
#pragma unroll
        for (int i = 0; i < 4; i++) {
            uint32_t h = f2tf(av[i]);
            Ah[0][aRow][aCol + i] = h;
            Al[0][aRow][aCol + i] = f2tf(av[i] - __uint_as_float(h));
            uint32_t hb = f2tf(bv[i]);
            Bh[0][bK][bCol + i] = hb;
            Bl[0][bK][bCol + i] = f2tf(bv[i] - __uint_as_float(hb));
        }
    }
    __syncthreads();

    for (int c = 0; c < nch; c++) {
        int buf = c & 1;
        // prefetch next chunk (global)
        if (c + 1 < nch) {
            int k0 = (c + 1) * GBK;
            ra = make_float4(0.f, 0.f, 0.f, 0.f);
            if (grow0 < M) ra = *reinterpret_cast<const float4*>(Ablk + (size_t)aRow * K + k0 + aCol);
            rb = *reinterpret_cast<const float4*>(Bblk + (size_t)(k0 + bK) * HDIM + bCol);
        }

        // load fragments from smem
        uint32_t ah[2][4], al[2][4];
#pragma unroll
        for (int mt = 0; mt < 2; mt++) {
            int r0 = wm * 32 + mt * 16 + g;
            ah[mt][0] = Ah[buf][r0][tg];
            ah[mt][1] = Ah[buf][r0 + 8][tg];
            ah[mt][2] = Ah[buf][r0][tg + 4];
            ah[mt][3] = Ah[buf][r0 + 8][tg + 4];
            al[mt][0] = Al[buf][r0][tg];
            al[mt][1] = Al[buf][r0 + 8][tg];
            al[mt][2] = Al[buf][r0][tg + 4];
            al[mt][3] = Al[buf][r0 + 8][tg + 4];
        }
        uint32_t bh[8][2], bl[8][2];
#pragma unroll
        for (int nt = 0; nt < 8; nt++) {
            int col = wn * 64 + nt * 8 + g;
            bh[nt][0] = Bh[buf][tg][col];
            bh[nt][1] = Bh[buf][tg + 4][col];
            bl[nt][0] = Bl[buf][tg][col];
            bl[nt][1] = Bl[buf][tg + 4][col];
        }

        // 3xTF32: hi*hi + hi*lo + lo*hi
#pragma unroll
        for (int mt = 0; mt < 2; mt++)
#pragma unroll
            for (int nt = 0; nt < 8; nt++) {
                mma8(acc[mt][nt], ah[mt], bh[nt]);
                mma8(acc[mt][nt], ah[mt], bl[nt]);
                mma8(acc[mt][nt], al[mt], bh[nt]);
            }

        // store next chunk into the other buffer
        if (c + 1 < nch) {
            int nb = buf ^ 1;
            float av[4] = {ra.x, ra.y, ra.z, ra.w};
            float bv[4] = {rb.x, rb.y, rb.z, rb.w};
#pragma unroll
            for (int i = 0; i < 4; i++) {
                uint32_t h = f2tf(av[i]);
                Ah[nb][aRow][aCol + i] = h;
                Al[nb][aRow][aCol + i] = f2tf(av[i] - __uint_as_float(h));
                uint32_t hb = f2tf(bv[i]);
                Bh[nb][bK][bCol + i] = hb;
                Bl[nb][bK][bCol + i] = f2tf(bv[i] - __uint_as_float(hb));
            }
        }
        __syncthreads();
    }

    // epilogue: float2 stores (cols 2*tg, 2*tg+1 are adjacent)
#pragma unroll
    for (int mt = 0; mt < 2; mt++) {
        int rbase = by * GBM + wm * 32 + mt * 16 + g;
#pragma unroll
        for (int nt = 0; nt < 8; nt++) {
            int col = bx * GBN + wn * 64 + nt * 8 + 2 * tg;
            if (rbase < M)
                *reinterpret_cast<float2*>(C + (size_t)rbase * HDIM + col) =
                    make_float2(acc[mt][nt][0], acc[mt][nt][1]);
            if (rbase + 8 < M)
                *reinterpret_cast<float2*>(C + (size_t)(rbase + 8) * HDIM + col) =
                    make_float2(acc[mt][nt][2], acc[mt][nt][3]);
        }
    }
}

// ---------------- per-node attention logits: alpha_s, alpha_d ----------------
__global__ void k_alpha(const float* __restrict__ h,
                        const float* __restrict__ avs,
                        const float* __restrict__ avd) {
    int gw = (blockIdx.x * blockDim.x + threadIdx.x) >> 5;
    int lane = threadIdx.x & 31;
    if (gw >= NN) return;
    const float* hr = h + (size_t)gw * HDIM;
    float accS[4] = {0.f, 0.f, 0.f, 0.f};
    float accD[4] = {0.f, 0.f, 0.f, 0.f};
#pragma unroll
    for (int k = 0; k < 8; k++) {
        int f = lane + 32 * k;
        float hv = hr[f];
        accS[k >> 1] += hv * __ldg(&avs[f]);
        accD[k >> 1] += hv * __ldg(&avd[f]);
    }
#pragma unroll
    for (int off = 16; off >= 1; off >>= 1) {
#pragma unroll
        for (int hh = 0; hh < 4; hh++) {
            accS[hh] += __shfl_xor_sync(FULL, accS[hh], off);
            accD[hh] += __shfl_xor_sync(FULL, accD[hh], off);
        }
    }
    if (lane == 0) {
#pragma unroll
        for (int hh = 0; hh < 4; hh++) {
            g_as[gw * 4 + hh] = accS[hh];
            g_ad[gw * 4 + hh] = accD[hh];
        }
    }
}

// ---------------- one-pass online-softmax aggregation (warp per dst node) ----
__global__ void k_agg(const float* __restrict__ h,
                      const float* __restrict__ bias,
                      float* __restrict__ out, int elu) {
    int gw = (blockIdx.x * blockDim.x + threadIdx.x) >> 5;
    int lane = threadIdx.x & 31;
    if (gw >= NN) return;

    float adl = (lane < 4) ? g_ad[gw * 4 + lane] : 0.f;
    int jb = __ldg(&g_rowptr[gw]), je = __ldg(&g_rowptr[gw + 1]);

    float acc[8] = {0.f, 0.f, 0.f, 0.f, 0.f, 0.f, 0.f, 0.f};
    float m[4] = {-INFINITY, -INFINITY, -INFINITY, -INFINITY};
    float ssum[4] = {0.f, 0.f, 0.f, 0.f};

    int src_next = (jb < je) ? __ldg(&g_col[jb]) : 0;
    for (int j = jb; j < je; j++) {
        int src = src_next;
        if (j + 1 < je) src_next = __ldg(&g_col[j + 1]);  // prefetch next index

        float ev = 0.f;
        if (lane < 4) {
            float e = __ldg(&g_as[src * 4 + lane]) + adl;
            ev = e > 0.f ? e : 0.2f * e;  // leaky relu
        }
        float e4[4];
        e4[0] = __shfl_sync(FULL, ev, 0);
        e4[1] = __shfl_sync(FULL, ev, 1);
        e4[2] = __shfl_sync(FULL, ev, 2);
        e4[3] = __shfl_sync(FULL, ev, 3);

        float sc[4], w[4];
#pragma unroll
        for (int hh = 0; hh < 4; hh++) {
            if (e4[hh] <= m[hh]) {
                sc[hh] = 1.f;
                w[hh] = __expf(e4[hh] - m[hh]);
            } else {
                sc[hh] = __expf(m[hh] - e4[hh]);  // exp(-inf)=0 on first edge
                w[hh] = 1.f;
                m[hh] = e4[hh];
            }
            ssum[hh] = ssum[hh] * sc[hh] + w[hh];
        }
        const float* hr = h + (size_t)src * HDIM + lane;
#pragma unroll
        for (int k = 0; k < 8; k++) {
            float xv = __ldg(hr + 32 * k);
            int hh = k >> 1;
            acc[k] = acc[k] * sc[hh] + w[hh] * xv;
        }
    }
#pragma unroll
    for (int k = 0; k < 8; k++) {
        int f = lane + 32 * k;
        int hh = k >> 1;
        float v = acc[k] / (ssum[hh] + 1e-16f) + __ldg(&bias[f]);
        if (elu) v = v > 0.f ? v : expm1f(v);
        out[(size_t)gw * HDIM + f] = v;
    }
}

// ---------------- final linear + log_softmax (warp per node) ----------------
__global__ void k_final(const float* __restrict__ h,
                        const float* __restrict__ Wl,
                        const float* __restrict__ bl,
                        float* __restrict__ out) {
    int gw = (blockIdx.x * blockDim.x + threadIdx.x) >> 5;
    int lane = threadIdx.x & 31;
    if (gw >= NN) return;

    int c0 = lane;
    int c1 = lane + 32;
    bool v1 = (c1 < NCLS);
    float a0 = __ldg(&bl[c0]);
    float a1 = v1 ? __ldg(&bl[c1]) : 0.f;
    const float* hr = h + (size_t)gw * HDIM;

    for (int kb = 0; kb < 8; kb++) {
        float xv = hr[kb * 32 + lane];
#pragma unroll
        for (int t = 0; t < 32; t++) {
            float xk = __shfl_sync(FULL, xv, t);
            int k = kb * 32 + t;
            a0 += xk * __ldg(&Wl[k * NCLS + c0]);
            if (v1) a1 += xk * __ldg(&Wl[k * NCLS + c1]);
        }
    }
    float mx = v1 ? fmaxf(a0, a1) : a0;
#pragma unroll
    for (int off = 16; off >= 1; off >>= 1) mx = fmaxf(mx, __shfl_xor_sync(FULL, mx, off));
    float se = __expf(a0 - mx) + (v1 ? __expf(a1 - mx) : 0.f);
#pragma unroll
    for (int off = 16; off >= 1; off >>= 1) se += __shfl_xor_sync(FULL, se, off);
    float lse = mx + __logf(se);
    out[(size_t)gw * NCLS + c0] = a0 - lse;
    if (v1) out[(size_t)gw * NCLS + c1] = a1 - lse;
}

// ---------------- launcher ----------------
extern "C" void kernel_launch(void* const* d_in, const int* in_sizes, int n_in,
                              void* d_out, int out_size) {
    const float* x   = (const float*)d_in[0];
    const void*  ei  = d_in[1];   // int32 or int64, detected on device
    const float* W1  = (const float*)d_in[2];
    const float* as1 = (const float*)d_in[3];
    const float* ad1 = (const float*)d_in[4];
    const float* b1  = (const float*)d_in[5];
    const float* W2  = (const float*)d_in[6];
    const float* as2 = (const float*)d_in[7];
    const float* ad2 = (const float*)d_in[8];
    const float* b2  = (const float*)d_in[9];
    const float* W3  = (const float*)d_in[10];
    const float* as3 = (const float*)d_in[11];
    const float* ad3 = (const float*)d_in[12];
    const float* b3  = (const float*)d_in[13];
    const float* Wl  = (const float*)d_in[14];
    const float* bl  = (const float*)d_in[15];
    float* out = (float*)d_out;

    float *ph, *pt;
    cudaGetSymbolAddress((void**)&ph, g_h);
    cudaGetSymbolAddress((void**)&pt, g_t);

    // CSR build
    k_detect<<<1, 32>>>(ei);
    k_deg_init<<<(NN + 255) / 256, 256>>>();
    k_deg_count<<<(EE + 255) / 256, 256>>>(ei);
    k_scan1<<<NBLK, SCB>>>();
    k_scan2<<<1, 32>>>();
    k_scan3<<<(NN + 255) / 256, 256>>>();
    k_fill<<<(ETOT + 255) / 256, 256>>>(ei);

    dim3 gemmGrid(HDIM / GBN, (NN + GBM - 1) / GBM);
    const int wgrid = (NN * 32 + 255) / 256;  // warp per node

    // layer 1
    k_mma<<<gemmGrid, 256>>>(x, W1, ph, NN, FIN);
    k_alpha<<<wgrid, 256>>>(ph, as1, ad1);
    k_agg<<<wgrid, 256>>>(ph, b1, pt, 1);
    // layer 2
    k_mma<<<gemmGrid, 256>>>(pt, W2, ph, NN, HDIM);
    k_alpha<<<wgrid, 256>>>(ph, as2, ad2);
    k_agg<<<wgrid, 256>>>(ph, b2, pt, 1);
    // layer 3
    k_mma<<<gemmGrid, 256>>>(pt, W3, ph, NN, HDIM);
    k_alpha<<<wgrid, 256>>>(ph, as3, ad3);
    k_agg<<<wgrid, 256>>>(ph, b3, pt, 1);
    // classifier + log_softmax
    k_final<<<wgrid, 256>>>(pt, Wl, bl, out);
}